// round 16
// baseline (speedup 1.0000x reference)
#include <cuda_runtime.h>
#include <cuda_fp16.h>
#include <math.h>
#include <float.h>
#include <stdint.h>

#define NTOK 4096
#define E_   32
#define SLOTS 8
#define DUMP_SLOT (NTOK * SLOTS)
#define SHARP_ 16.0f

__device__ float    g_IL[NTOK * E_];
__device__ float    g_glogp[3 * NTOK * 8];
__device__ int      g_cnt[E_];
__device__ int      g_tokid[E_ * NTOK];
__device__ int      g_slot [E_ * NTOK];
__device__ float    g_w4[NTOK * SLOTS];
__device__ int      g_e4[NTOK * SLOTS];
__device__ int      g_scnt[NTOK];
__device__ float    g_part[(NTOK * SLOTS + 1) * 512];
__device__ unsigned g_minenc, g_maxenc;
__device__ float    g_M[128];
__device__ float    g_C[32];
__device__ uint32_t g_We1h[E_ * 65536];
__device__ uint32_t g_We2h[E_ * 65536];
__device__ uint32_t g_Hh  [NTOK * 256];
__device__ uint32_t g_Hlo [NTOK * 256];
__device__ uint32_t g_Wexth[256 * 288];
__device__ uint32_t g_Wextl[256 * 288];

__device__ __forceinline__ unsigned encf(float x) {
    unsigned u = __float_as_uint(x);
    return (u & 0x80000000u) ? ~u : (u | 0x80000000u);
}
__device__ __forceinline__ float decf(unsigned e) {
    return (e & 0x80000000u) ? __uint_as_float(e ^ 0x80000000u) : __uint_as_float(~e);
}
__device__ __forceinline__ float gelu_exact(float x) {
    return 0.5f * x * (1.0f + erff(x * 0.70710678118654752f));
}
__device__ __forceinline__ uint32_t pack_h2(float a, float b) {
    __half2 h = __floats2half2_rn(a, b);
    return *(uint32_t*)&h;
}
__device__ __forceinline__ void split_h2(float a, float b, uint32_t& hi, uint32_t& lo) {
    __half ha = __float2half_rn(a), hb = __float2half_rn(b);
    float ra = a - __half2float(ha), rb = b - __half2float(hb);
    __half2 h = __halves2half2(ha, hb);
    hi = *(uint32_t*)&h;
    lo = pack_h2(ra, rb);
}
__device__ __forceinline__ void mma16(float* c, const uint32_t* a, uint32_t b0, uint32_t b1) {
    asm volatile(
        "mma.sync.aligned.m16n8k16.row.col.f32.f16.f16.f32 "
        "{%0,%1,%2,%3},{%4,%5,%6,%7},{%8,%9},{%0,%1,%2,%3};"
        : "+f"(c[0]), "+f"(c[1]), "+f"(c[2]), "+f"(c[3])
        : "r"(a[0]), "r"(a[1]), "r"(a[2]), "r"(a[3]), "r"(b0), "r"(b1));
}
__device__ __forceinline__ void cp_async16(uint32_t saddr, const void* g) {
    asm volatile("cp.async.ca.shared.global [%0], [%1], 16;" :: "r"(saddr), "l"(g));
}
__device__ __forceinline__ void cp_async8(uint32_t saddr, const void* g) {
    asm volatile("cp.async.ca.shared.global [%0], [%1], 8;" :: "r"(saddr), "l"(g));
}
__device__ __forceinline__ void cp_commit() { asm volatile("cp.async.commit_group;"); }
template<int N> __device__ __forceinline__ void cp_wait() {
    asm volatile("cp.async.wait_group %0;" :: "n"(N));
}

// ---------------- K0 ----------------
__global__ void k_init(const float* __restrict__ Wfe, const float* __restrict__ bfe,
                       const float* __restrict__ Win_f) {
    int tid = threadIdx.x;
    if (tid < E_) g_cnt[tid] = 0;
    if (tid == 255) { g_minenc = 0xFFFFFFFFu; g_maxenc = 0u; }
    if (tid < 128) {
        int g = tid >> 4, f = (tid >> 2) & 3, s = tid & 3;
        float acc = 0.f;
        #pragma unroll 4
        for (int e = 0; e < 64; e++)
            acc += Wfe[(g * 4 + f) * 64 + e] * Win_f[(g * 64 + e) * 4 + s];
        g_M[tid] = acc;
    } else if (tid < 160) {
        int j = tid - 128; int g = j >> 2, s = j & 3;
        float acc = 0.f;
        #pragma unroll 4
        for (int e = 0; e < 64; e++)
            acc += bfe[g * 64 + e] * Win_f[(g * 64 + e) * 4 + s];
        g_C[j] = acc;
    }
}

__global__ void k_minmax(const float* __restrict__ feat, int n) {
    unsigned lmin = 0xFFFFFFFFu, lmax = 0u;
    for (int i = blockIdx.x * blockDim.x + threadIdx.x; i < n; i += gridDim.x * blockDim.x) {
        unsigned e = encf(feat[i]);
        lmin = min(lmin, e); lmax = max(lmax, e);
    }
    #pragma unroll
    for (int o = 16; o; o >>= 1) {
        lmin = min(lmin, __shfl_down_sync(0xFFFFFFFFu, lmin, o));
        lmax = max(lmax, __shfl_down_sync(0xFFFFFFFFu, lmax, o));
    }
    if ((threadIdx.x & 31) == 0) { atomicMin(&g_minenc, lmin); atomicMax(&g_maxenc, lmax); }
}

__global__ __launch_bounds__(256) void k_cvt_r(const float* __restrict__ H,
                                               const float* __restrict__ Wr1,
                                               const float* __restrict__ Win_h) {
    int id = blockIdx.x * 256 + threadIdx.x;
    if (id < 262144) {
        int t = id >> 6, p = id & 63;
        const float4* src = (const float4*)&H[(size_t)t * 512 + p * 8];
        float4 a = src[0], c = src[1];
        uint4 oh, ol;
        split_h2(a.x, a.y, oh.x, ol.x); split_h2(a.z, a.w, oh.y, ol.y);
        split_h2(c.x, c.y, oh.z, ol.z); split_h2(c.z, c.w, oh.w, ol.w);
        ((uint4*)g_Hh)[(size_t)t * 64 + p]  = oh;
        ((uint4*)g_Hlo)[(size_t)t * 64 + p] = ol;
    } else if (id < 278528) {
        int v = id - 262144;
        int r = v >> 6, c4 = (v & 63) * 4;
        const float* b0 = Wr1 + (size_t)(2 * r) * 256 + c4;
        const float* b1 = Wr1 + (size_t)(2 * r + 1) * 256 + c4;
        float4 a = *(const float4*)b0;
        float4 c = *(const float4*)b1;
        uint32_t hi, lo;
        split_h2(a.x, c.x, hi, lo); g_Wexth[r * 288 + c4 + 0] = hi; g_Wextl[r * 288 + c4 + 0] = lo;
        split_h2(a.y, c.y, hi, lo); g_Wexth[r * 288 + c4 + 1] = hi; g_Wextl[r * 288 + c4 + 1] = lo;
        split_h2(a.z, c.z, hi, lo); g_Wexth[r * 288 + c4 + 2] = hi; g_Wextl[r * 288 + c4 + 2] = lo;
        split_h2(a.w, c.w, hi, lo); g_Wexth[r * 288 + c4 + 3] = hi; g_Wextl[r * 288 + c4 + 3] = lo;
    } else if (id < 286720) {
        int v = id - 278528;
        int r = v >> 5, j = v & 31;
        int g = j >> 2, s = j & 3;
        float v0 = Win_h[((size_t)g * 512 + 2 * r) * 4 + s];
        float v1 = Win_h[((size_t)g * 512 + 2 * r + 1) * 4 + s];
        uint32_t hi, lo;
        split_h2(v0, v1, hi, lo);
        g_Wexth[r * 288 + 256 + j] = hi;
        g_Wextl[r * 288 + 256 + j] = lo;
    }
}

__global__ __launch_bounds__(256) void k_cvt_w(const float* __restrict__ We1,
                                               const float* __restrict__ We2) {
    int id = blockIdx.x * 256 + threadIdx.x;
    {
        int e = id >> 14, rem = id & 16383;
        int kr = rem >> 6, n = (rem & 63) * 4;
        const float* base = We1 + ((size_t)e * 512 + 2 * kr) * 256 + n;
        float4 a = *(const float4*)base;
        float4 c = *(const float4*)(base + 256);
        uint4 o;
        o.x = pack_h2(a.x, c.x); o.y = pack_h2(a.y, c.y);
        o.z = pack_h2(a.z, c.z); o.w = pack_h2(a.w, c.w);
        ((uint4*)g_We1h)[((size_t)e * 65536 + kr * 256 + n) >> 2] = o;
    }
    {
        int e = id >> 14, rem = id & 16383;
        int kr = rem >> 7, n = (rem & 127) * 4;
        const float* base = We2 + ((size_t)e * 256 + 2 * kr) * 512 + n;
        float4 a = *(const float4*)base;
        float4 c = *(const float4*)(base + 512);
        uint4 o;
        o.x = pack_h2(a.x, c.x); o.y = pack_h2(a.y, c.y);
        o.z = pack_h2(a.z, c.z); o.w = pack_h2(a.w, c.w);
        ((uint4*)g_We2h)[((size_t)e * 65536 + kr * 512 + n) >> 2] = o;
    }
}

// ---------------- K1: router GEMM + fused glog projection ----------------
#define GXP 36
#define GWP 104
#define GXBUF (64 * GXP)
#define GWBUF (32 * GWP)
#define GH_SMEM_BYTES ((2 * GXBUF + 2 * GWBUF) * 4)

__global__ __launch_bounds__(256) void k_gh(const float* __restrict__ br1,
                                            const float* __restrict__ Wr2) {
    extern __shared__ uint32_t gsm[];
    uint32_t* Xs2 = gsm;
    uint32_t* Ws2 = gsm + 2 * GXBUF;
    const int cg = blockIdx.x, base = blockIdx.y * 64, tid = threadIdx.x;
    const int w = tid >> 5, lane = tid & 31, gid = lane >> 2, tig = lane & 3;
    const int mwarp = (w & 1) * 32, nwarp = (w >> 1) * 24;
    const uint32_t xs_sb = (uint32_t)__cvta_generic_to_shared(Xs2);
    const uint32_t ws_sb = (uint32_t)__cvta_generic_to_shared(Ws2);

    float acc[2][3][4];
    #pragma unroll
    for (int m8 = 0; m8 < 2; m8++)
        #pragma unroll
        for (int n8 = 0; n8 < 3; n8++)
            #pragma unroll
            for (int c = 0; c < 4; c++) acc[m8][n8][c] = 0.f;

    #pragma unroll
    for (int pc = 0; pc < 2; pc++) {
        #pragma unroll
        for (int j = 0; j < 2; j++) {
            int u = j * 256 + tid, row = u >> 3, xq = (u & 7) * 4;
            cp_async16(xs_sb + (pc * GXBUF + row * GXP + xq) * 4,
                       &g_Hh[(size_t)(base + row) * 256 + pc * 32 + xq]);
        }
        #pragma unroll
        for (int j = 0; j < 3; j++) {
            int u = j * 256 + tid, kr = u / 24, c4 = (u % 24) * 4;
            cp_async16(ws_sb + (pc * GWBUF + kr * GWP + c4) * 4,
                       &g_Wexth[(pc * 32 + kr) * 288 + cg * 96 + c4]);
        }
        cp_commit();
    }

    for (int i = 0; i < 24; i++) {
        if (i < 23) cp_wait<1>(); else cp_wait<0>();
        __syncthreads();
        const uint32_t* Xb = Xs2 + (i & 1) * GXBUF;
        const uint32_t* Wb = Ws2 + (i & 1) * GWBUF;
        #pragma unroll
        for (int ks = 0; ks < 4; ks++) {
            const int kh = ks * 8;
            uint32_t a[2][4];
            #pragma unroll
            for (int m8 = 0; m8 < 2; m8++) {
                int r0 = mwarp + m8 * 16 + gid;
                a[m8][0] = Xb[r0 * GXP + kh + tig];
                a[m8][1] = Xb[(r0 + 8) * GXP + kh + tig];
                a[m8][2] = Xb[r0 * GXP + kh + tig + 4];
                a[m8][3] = Xb[(r0 + 8) * GXP + kh + tig + 4];
            }
            #pragma unroll
            for (int n8 = 0; n8 < 3; n8++) {
                int ncol = nwarp + n8 * 8 + gid;
                uint32_t b0 = Wb[(kh + tig) * GWP + ncol];
                uint32_t b1 = Wb[(kh + tig + 4) * GWP + ncol];
                mma16(acc[0][n8], a[0], b0, b1);
                mma16(acc[1][n8], a[1], b0, b1);
            }
        }
        __syncthreads();
        if (i + 2 < 24) {
            int kci = i + 2, buf = i & 1, seg = kci >> 3, kloc = kci & 7;
            const uint32_t* Asrc = (seg < 2) ? g_Hh : g_Hlo;
            const uint32_t* Wsrc = (seg == 1) ? g_Wextl : g_Wexth;
            #pragma unroll
            for (int j = 0; j < 2; j++) {
                int u = j * 256 + tid, row = u >> 3, xq = (u & 7) * 4;
                cp_async16(xs_sb + (buf * GXBUF + row * GXP + xq) * 4,
                           &Asrc[(size_t)(base + row) * 256 + kloc * 32 + xq]);
            }
            #pragma unroll
            for (int j = 0; j < 3; j++) {
                int u = j * 256 + tid, kr = u / 24, c4 = (u % 24) * 4;
                cp_async16(ws_sb + (buf * GWBUF + kr * GWP + c4) * 4,
                           &Wsrc[(kloc * 32 + kr) * 288 + cg * 96 + c4]);
            }
            cp_commit();
        }
    }

    float part[4][8];
    #pragma unroll
    for (int r = 0; r < 4; r++)
        #pragma unroll
        for (int q = 0; q < 8; q++) part[r][q] = 0.f;

    #pragma unroll
    for (int m8 = 0; m8 < 2; m8++) {
        #pragma unroll
        for (int c2 = 0; c2 < 2; c2++) {
            const int r = m8 * 2 + c2;
            const int row = base + mwarp + m8 * 16 + gid + (c2 ? 8 : 0);
            #pragma unroll
            for (int n8 = 0; n8 < 3; n8++) {
                int col0 = cg * 96 + nwarp + n8 * 8 + 2 * tig;
                float a0 = acc[m8][n8][c2 * 2 + 0];
                float a1 = acc[m8][n8][c2 * 2 + 1];
                if (col0 < 256) {
                    float v0 = gelu_exact(a0 + br1[col0]);
                    float v1 = gelu_exact(a1 + br1[col0 + 1]);
                    float4 w0a = *(const float4*)&Wr2[col0 * 8];
                    float4 w0b = *(const float4*)&Wr2[col0 * 8 + 4];
                    float4 w1a = *(const float4*)&Wr2[col0 * 8 + 8];
                    float4 w1b = *(const float4*)&Wr2[col0 * 8 + 12];
                    part[r][0] += v0 * w0a.x + v1 * w1a.x;
                    part[r][1] += v0 * w0a.y + v1 * w1a.y;
                    part[r][2] += v0 * w0a.z + v1 * w1a.z;
                    part[r][3] += v0 * w0a.w + v1 * w1a.w;
                    part[r][4] += v0 * w0b.x + v1 * w1b.x;
                    part[r][5] += v0 * w0b.y + v1 * w1b.y;
                    part[r][6] += v0 * w0b.z + v1 * w1b.z;
                    part[r][7] += v0 * w0b.w + v1 * w1b.w;
                } else {
                    *(float2*)&g_IL[(size_t)row * 32 + (col0 - 256)] = make_float2(a0, a1);
                }
            }
        }
    }

    #pragma unroll
    for (int r = 0; r < 4; r++)
        #pragma unroll
        for (int q = 0; q < 8; q++) {
            float v = part[r][q];
            v += __shfl_xor_sync(0xFFFFFFFFu, v, 1);
            v += __shfl_xor_sync(0xFFFFFFFFu, v, 2);
            part[r][q] = v;
        }

    __syncthreads();
    float* parts = (float*)gsm;
    if (tig == 0) {
        int wn = w >> 1;
        #pragma unroll
        for (int r = 0; r < 4; r++) {
            int rl = mwarp + (r >> 1) * 16 + gid + ((r & 1) ? 8 : 0);
            #pragma unroll
            for (int q = 0; q < 8; q++)
                parts[(wn * 64 + rl) * 8 + q] = part[r][q];
        }
    }
    __syncthreads();
    #pragma unroll
    for (int j = 0; j < 2; j++) {
        int idx = tid * 2 + j, row = idx >> 3, q = idx & 7;
        float v = parts[(0 * 64 + row) * 8 + q] + parts[(1 * 64 + row) * 8 + q]
                + parts[(2 * 64 + row) * 8 + q] + parts[(3 * 64 + row) * 8 + q];
        g_glogp[((size_t)cg * NTOK + base + row) * 8 + q] = v;
    }
}

// ---------------- K2: per-token routing ----------------
__global__ __launch_bounds__(256) void k_route(
    const float* __restrict__ feat, const float* __restrict__ br2,
    const float* __restrict__ bin_b)
{
    __shared__ float feat_s[32];
    __shared__ float glog_s[8], ilog_s[32], score_s[8], gw_s[8], cw_s[32], w_s[32];
    __shared__ int scnt_s;
    const int t = blockIdx.x, tid = threadIdx.x;

    if (tid == 0) scnt_s = 0;
    if (tid < 32) feat_s[tid] = feat[(size_t)t * 32 + tid];
    if (tid < 8)
        glog_s[tid] = g_glogp[((size_t)0 * NTOK + t) * 8 + tid]
                    + g_glogp[((size_t)1 * NTOK + t) * 8 + tid]
                    + g_glogp[((size_t)2 * NTOK + t) * 8 + tid] + br2[tid];
    __syncthreads();

    const bool in01 = (decf(g_minenc) >= -1e-6f) && (decf(g_maxenc) <= 1.0f + 1e-6f);
    if (tid < 8) {
        float sc = 0.f;
        #pragma unroll
        for (int f = 0; f < 4; f++) {
            float x = feat_s[tid * 4 + f];
            float r = in01 ? fminf(fmaxf(x, 0.f), 1.f)
                           : fminf(fmaxf(0.5f * (1.f + erff(x * 0.70710678118654752f)), 0.f), 1.f);
            sc += r;
        }
        score_s[tid] = sc * 0.25f;
    }
    __syncthreads();

    if (tid < 32) {
        int g = tid >> 2, s = tid & 3;
        float q = g_C[tid];
        #pragma unroll
        for (int f = 0; f < 4; f++)
            q += feat_s[g * 4 + f] * g_M[g * 16 + f * 4 + s];
        float c = (float)s * (1.0f / 3.0f);
        float dd = score_s[g] - c;
        ilog_s[tid] = q + g_IL[(size_t)t * 32 + tid] + bin_b[tid] - SHARP_ * dd * dd;
    }
    __syncthreads();

    if (tid == 0) {
        float m1 = -FLT_MAX, m2 = -FLT_MAX;
        #pragma unroll
        for (int g = 0; g < 8; g++) {
            float v = glog_s[g];
            if (v > m1) { m2 = m1; m1 = v; } else if (v > m2) m2 = v;
        }
        float ex[8]; float sum = 0.f;
        #pragma unroll
        for (int g = 0; g < 8; g++) {
            float v = glog_s[g];
            if (v >= m2) { ex[g] = expf(v - m1); sum += ex[g]; } else ex[g] = 0.f;
        }
        #pragma unroll
        for (int g = 0; g < 8; g++) gw_s[g] = ex[g] / sum;
    }
    if (tid < 8) {
        float m1 = -FLT_MAX, m2 = -FLT_MAX;
        #pragma unroll
        for (int s = 0; s < 4; s++) {
            float v = ilog_s[tid * 4 + s];
            if (v > m1) { m2 = m1; m1 = v; } else if (v > m2) m2 = v;
        }
        float ex[4]; float sum = 0.f;
        #pragma unroll
        for (int s = 0; s < 4; s++) {
            float v = ilog_s[tid * 4 + s];
            if (v >= m2) { ex[s] = expf(v - m1); sum += ex[s]; } else ex[s] = 0.f;
        }
        #pragma unroll
        for (int s = 0; s < 4; s++) cw_s[tid * 4 + s] = ex[s] / sum;
    }
    __syncthreads();
    if (tid < 32) w_s[tid] = gw_s[tid >> 2] * cw_s[tid];
    __syncthreads();

    if (tid < 32 && w_s[tid] > 0.f) {
        int j = atomicAdd(&scnt_s, 1);
        if (j < SLOTS) {
            g_w4[t * SLOTS + j] = w_s[tid];
            g_e4[t * SLOTS + j] = tid;
            int pos = atomicAdd(&g_cnt[tid], 1);
            g_tokid[tid * NTOK + pos] = t;
            g_slot [tid * NTOK + pos] = t * SLOTS + j;
        }
    }
    __syncthreads();
    if (tid == 0) g_scnt[t] = min(scnt_s, SLOTS);
}

// ---------------- K3: expert FFN, fp16 mma, 3-stage cp.async, 1 sync/chunk ----------------
#define XP2 20
#define WP2 264
#define HP2 132
#define XBUF (64 * XP2)          // 1280
#define WBUF (16 * WP2)          // 4224
#define OFF_TOK   0
#define OFF_SLOT  64
#define OFF_B1    128
#define OFF_XS    384
#define OFF_WS    (OFF_XS + 3 * XBUF)      // 4224
#define OFF_H1    (OFF_WS + 3 * WBUF)      // 16896
#define SMEM_WORDS (OFF_H1 + 64 * HP2)     // 25344
#define SMEM_BYTES (SMEM_WORDS * 4)        // 101376

__global__ __launch_bounds__(256, 2) void k_expert_mma(const float* __restrict__ be1)
{
    extern __shared__ uint32_t smu[];
    int*      tok_s  = (int*)smu;
    int*      slot_s = (int*)(smu + OFF_SLOT);
    float*    bias_s = (float*)(smu + OFF_B1);
    uint32_t* Xs2    = smu + OFF_XS;
    uint32_t* Ws2    = smu + OFF_WS;
    uint32_t* H1s2   = smu + OFF_H1;

    const int e = blockIdx.x;
    const int n = g_cnt[e];
    const int base = blockIdx.y * 64;
    if (base >= n) return;

    const int tid  = threadIdx.x;
    const int w    = tid >> 5;
    const int lane = tid & 31;
    const int gid  = lane >> 2;
    const int tig  = lane & 3;
    const int mwarp = (w & 1) * 32;
    const int nwarp = (w >> 1) * 64;

    if (tid < 64) {
        int idx = base + tid;
        if (idx < n) { tok_s[tid] = g_tokid[e * NTOK + idx]; slot_s[tid] = g_slot[e * NTOK + idx]; }
        else         { tok_s[tid] = g_tokid[e * NTOK + base]; slot_s[tid] = DUMP_SLOT; }
    }
    bias_s[tid] = be1[e * 256 + tid];
    __syncthreads();

    const uint32_t xs_sb = (uint32_t)__cvta_generic_to_shared(Xs2);
    const uint32_t ws_sb = (uint32_t)__cvta_generic_to_shared(Ws2);
    const uint32_t* W1h = g_We1h + (size_t)e * 65536;
    const uint32_t* W2h = g_We2h + (size_t)e * 65536;

    #define STAGE_XW1(kci, b) do { \
        _Pragma("unroll") \
        for (int _j = 0; _j < 2; _j++) { \
            int _u = tid * 2 + _j; \
            int _t = _u >> 3, _p = _u & 7; \
            cp_async8(xs_sb + ((b) * XBUF + _t * XP2 + _p * 2) * 4, \
                      &g_Hh[(size_t)tok_s[_t] * 256 + (kci) * 16 + _p * 2]); \
        } \
        _Pragma("unroll") \
        for (int _j = 0; _j < 4; _j++) { \
            int _u = _j * 256 + tid; \
            int _kr = _u >> 6, _c = (_u & 63) * 4; \
            cp_async16(ws_sb + ((b) * WBUF + _kr * WP2 + _c) * 4, \
                       &W1h[((kci) * 16 + _kr) * 256 + _c]); \
        } \
        cp_commit(); \
    } while (0)
    #define STAGE_W2(kci, half, b) do { \
        _Pragma("unroll") \
        for (int _j = 0; _j < 4; _j++) { \
            int _u = _j * 256 + tid; \
            int _kr = _u >> 6, _c = (_u & 63) * 4; \
            cp_async16(ws_sb + ((b) * WBUF + _kr * WP2 + _c) * 4, \
                       &W2h[(size_t)((kci) * 16 + _kr) * 512 + (half) * 256 + _c]); \
        } \
        cp_commit(); \
    } while (0)

    float acc[2][8][4];

    // ================= phase 1: h1 = gelu(X @ We1 + b1), 16 chunks, 3-stage =================
    #pragma unroll
    for (int m8 = 0; m8 < 2; m8++)
        #pragma unroll
        for (int n8 = 0; n8 < 8; n8++)
            #pragma unroll
            for (int c = 0; c < 4; c++) acc[m8][n8][c] = 0.f;

    STAGE_XW1(0, 0);
    STAGE_XW1(1, 1);

    for (int i = 0; i < 16; i++) {
        if (i < 15) cp_wait<1>(); else cp_wait<0>();
        __syncthreads();
        // stage next into the buffer freed by this sync
        if (i + 2 < 16) STAGE_XW1(i + 2, (i + 2) % 3);

        const uint32_t* Xb = Xs2 + (i % 3) * XBUF;
        const uint32_t* Wb = Ws2 + (i % 3) * WBUF;
        #pragma unroll
        for (int ks = 0; ks < 2; ks++) {
            const int kh = ks * 8;
            uint32_t a[2][4];
            #pragma unroll
            for (int m8 = 0; m8 < 2; m8++) {
                int r0 = mwarp + m8 * 16 + gid;
                a[m8][0] = Xb[r0 * XP2 + kh + tig];
                a[m8][1] = Xb[(r0 + 8) * XP2 + kh + tig];
                a[m8][2] = Xb[r0 * XP2 + kh + tig + 4];
                a[m8][3] = Xb[(r0 + 8) * XP2 + kh + tig + 4];
            }
            #pragma unroll
            for (int n8 = 0; n8 < 8; n8++) {
                int ncol = nwarp + n8 * 8 + gid;
                uint32_t b0 = Wb[(kh + tig) * WP2 + ncol];
                uint32_t b1 = Wb[(kh + tig + 4) * WP2 + ncol];
                mma16(acc[0][n8], a[0], b0, b1);
                mma16(acc[1][n8], a[1], b0, b1);
            }
        }
    }

    // drain sync: everyone done with phase-1 buffers before W2 staging reuses them
    __syncthreads();
    STAGE_W2(0, 0, 0);
    STAGE_W2(1, 0, 1);

    // epilogue 1 (overlaps W2 stage 0,1): bias + gelu -> H1s2
    #pragma unroll
    for (int m8 = 0; m8 < 2; m8++) {
        #pragma unroll
        for (int c2 = 0; c2 < 2; c2++) {
            int row = mwarp + m8 * 16 + gid + (c2 ? 8 : 0);
            #pragma unroll
            for (int n8 = 0; n8 < 8; n8++) {
                int col0 = nwarp + n8 * 8 + 2 * tig;
                float v0 = gelu_exact(acc[m8][n8][c2 * 2 + 0] + bias_s[col0]);
                float v1 = gelu_exact(acc[m8][n8][c2 * 2 + 1] + bias_s[col0 + 1]);
                H1s2[row * HP2 + (col0 >> 1)] = pack_h2(v0, v1);
            }
        }
    }
    __syncthreads();

    // ================= phase 2: part = h1 @ We2, 2 halves x 8 chunks, 3-stage =================
    #pragma unroll
    for (int half = 0; half < 2; half++) {
        #pragma unroll
        for (int m8 = 0; m8 < 2; m8++)
            #pragma unroll
            for (int n8 = 0; n8 < 8; n8++)
                #pragma unroll
                for (int c = 0; c < 4; c++) acc[m8][n8][c] = 0.f;

        if (half == 1) {
            // buffers free after previous half's drain; stage first two chunks
            STAGE_W2(0, 1, 0);
            STAGE_W2(1, 1, 1);
        }

        for (int i = 0; i < 8; i++) {
            if (i < 7) cp_wait<1>(); else cp_wait<0>();
            __syncthreads();
            if (i + 2 < 8) STAGE_W2(i + 2, half, (i + 2) % 3);

            const uint32_t* Wb = Ws2 + (i % 3) * WBUF;
            const int kc = i * 32;
            #pragma unroll
            for (int ks = 0; ks < 2; ks++) {
                const int kh = ks * 8;
                const int ah = (kc >> 1) + kh;
                uint32_t a[2][4];
                #pragma unroll
                for (int m8 = 0; m8 < 2; m8++) {
                    int r0 = mwarp + m8 * 16 + gid;
                    a[m8][0] = H1s2[r0 * HP2 + ah + tig];
                    a[m8][1] = H1s2[(r0 + 8) * HP2 + ah + tig];
                    a[m8][2] = H1s2[r0 * HP2 + ah + tig + 4];
                    a[m8][3] = H1s2[(r0 + 8) * HP2 + ah + tig + 4];
                }
                #pragma unroll
                for (int n8 = 0; n8 < 8; n8++) {
                    int ncol = nwarp + n8 * 8 + gid;
                    uint32_t b0 = Wb[(kh + tig) * WP2 + ncol];
                    uint32_t b1 = Wb[(kh + tig + 4) * WP2 + ncol];
                    mma16(acc[0][n8], a[0], b0, b1);
                    mma16(acc[1][n8], a[1], b0, b1);
                }
            }
        }
        __syncthreads();   // drain before next half reuses buffers

        #pragma unroll
        for (int m8 = 0; m8 < 2; m8++) {
            #pragma unroll
            for (int c2 = 0; c2 < 2; c2++) {
                int row = mwarp + m8 * 16 + gid + (c2 ? 8 : 0);
                int sl = slot_s[row];
                float* dst = &g_part[(size_t)sl * 512 + half * 256 + nwarp + 2 * tig];
                #pragma unroll
                for (int n8 = 0; n8 < 8; n8++) {
                    float2 v = make_float2(acc[m8][n8][c2 * 2 + 0], acc[m8][n8][c2 * 2 + 1]);
                    *(float2*)(dst + n8 * 8) = v;
                }
            }
        }
    }
    #undef STAGE_XW1
    #undef STAGE_W2
}

// ---------------- K4: gather ----------------
__global__ __launch_bounds__(128) void k_gather(const float* __restrict__ be2,
                                                float* __restrict__ y) {
    const int t = blockIdx.x, tid = threadIdx.x;
    const int d = tid * 4;
    const int cnt = g_scnt[t];
    float4 acc = make_float4(0.f, 0.f, 0.f, 0.f);
    for (int j = 0; j < cnt; j++) {
        float wv = g_w4[t * SLOTS + j];
        int   ev = g_e4[t * SLOTS + j];
        float4 p = *(const float4*)&g_part[(size_t)(t * SLOTS + j) * 512 + d];
        float4 b = *(const float4*)&be2[ev * 512 + d];
        acc.x += wv * (p.x + b.x); acc.y += wv * (p.y + b.y);
        acc.z += wv * (p.z + b.z); acc.w += wv * (p.w + b.w);
    }
    *(float4*)&y[(size_t)t * 512 + d] = acc;
}

// ---------------- launch ----------------
extern "C" void kernel_launch(void* const* d_in, const int* in_sizes, int n_in,
                              void* d_out, int out_size) {
    (void)in_sizes; (void)n_in; (void)out_size;
    const float* hidden = (const float*)d_in[0];
    const float* feat   = (const float*)d_in[1];
    const float* Wr1    = (const float*)d_in[3];
    const float* br1    = (const float*)d_in[4];
    const float* Wr2    = (const float*)d_in[5];
    const float* br2    = (const float*)d_in[6];
    const float* Wfe    = (const float*)d_in[7];
    const float* bfe    = (const float*)d_in[8];
    const float* Win_h  = (const float*)d_in[9];
    const float* Win_f  = (const float*)d_in[10];
    const float* bin_b  = (const float*)d_in[11];
    const float* We1    = (const float*)d_in[12];
    const float* be1    = (const float*)d_in[13];
    const float* We2    = (const float*)d_in[14];
    const float* be2    = (const float*)d_in[15];
    float* y = (float*)d_out;

    static bool inited = false;
    static cudaStream_t s2;
    static cudaEvent_t evFork, evJoin;
    if (!inited) {
        cudaFuncSetAttribute(k_expert_mma, cudaFuncAttributeMaxDynamicSharedMemorySize, SMEM_BYTES);
        cudaFuncSetAttribute(k_gh, cudaFuncAttributeMaxDynamicSharedMemorySize, GH_SMEM_BYTES);
        cudaStreamCreateWithFlags(&s2, cudaStreamNonBlocking);
        cudaEventCreateWithFlags(&evFork, cudaEventDisableTiming);
        cudaEventCreateWithFlags(&evJoin, cudaEventDisableTiming);
        inited = true;
    }

    cudaEventRecord(evFork, 0);
    cudaStreamWaitEvent(s2, evFork, 0);
    k_init<<<1, 256, 0, s2>>>(Wfe, bfe, Win_f);
    k_minmax<<<64, 256, 0, s2>>>(feat, NTOK * 32);
    k_cvt_w<<<2048, 256, 0, s2>>>(We1, We2);
    cudaEventRecord(evJoin, s2);

    k_cvt_r<<<1120, 256>>>(hidden, Wr1, Win_h);
    k_gh<<<dim3(3, NTOK / 64), 256, GH_SMEM_BYTES>>>(br1, Wr2);

    cudaStreamWaitEvent(0, evJoin, 0);
    k_route<<<NTOK, 256>>>(feat, br2, bin_b);
    k_expert_mma<<<dim3(E_, NTOK / 64), 256, SMEM_BYTES>>>(be1);
    k_gather<<<NTOK, 128>>>(be2, y);
}

// round 17
// speedup vs baseline: 1.0982x; 1.0982x over previous
#include <cuda_runtime.h>
#include <cuda_fp16.h>
#include <math.h>
#include <float.h>
#include <stdint.h>

#define NTOK 4096
#define E_   32
#define SLOTS 8
#define DUMP_SLOT (NTOK * SLOTS)
#define SHARP_ 16.0f

__device__ float    g_IL[NTOK * E_];
__device__ float    g_glogp[3 * NTOK * 8];
__device__ int      g_cnt[E_];
__device__ int      g_tokid[E_ * NTOK];
__device__ int      g_slot [E_ * NTOK];
__device__ float    g_w4[NTOK * SLOTS];
__device__ int      g_e4[NTOK * SLOTS];
__device__ int      g_scnt[NTOK];
__device__ float    g_part[(NTOK * SLOTS + 1) * 512];
__device__ unsigned g_minenc, g_maxenc;
__device__ float    g_M[128];
__device__ float    g_C[32];
__device__ uint32_t g_We1h[E_ * 65536];
__device__ uint32_t g_We2h[E_ * 65536];
__device__ uint32_t g_Hh  [NTOK * 256];
__device__ uint32_t g_Hlo [NTOK * 256];
__device__ uint32_t g_Wexth[256 * 288];
__device__ uint32_t g_Wextl[256 * 288];

__device__ __forceinline__ unsigned encf(float x) {
    unsigned u = __float_as_uint(x);
    return (u & 0x80000000u) ? ~u : (u | 0x80000000u);
}
__device__ __forceinline__ float decf(unsigned e) {
    return (e & 0x80000000u) ? __uint_as_float(e ^ 0x80000000u) : __uint_as_float(~e);
}
__device__ __forceinline__ float gelu_exact(float x) {
    return 0.5f * x * (1.0f + erff(x * 0.70710678118654752f));
}
__device__ __forceinline__ uint32_t pack_h2(float a, float b) {
    __half2 h = __floats2half2_rn(a, b);
    return *(uint32_t*)&h;
}
__device__ __forceinline__ void split_h2(float a, float b, uint32_t& hi, uint32_t& lo) {
    __half ha = __float2half_rn(a), hb = __float2half_rn(b);
    float ra = a - __half2float(ha), rb = b - __half2float(hb);
    __half2 h = __halves2half2(ha, hb);
    hi = *(uint32_t*)&h;
    lo = pack_h2(ra, rb);
}
__device__ __forceinline__ void mma16(float* c, const uint32_t* a, uint32_t b0, uint32_t b1) {
    asm volatile(
        "mma.sync.aligned.m16n8k16.row.col.f32.f16.f16.f32 "
        "{%0,%1,%2,%3},{%4,%5,%6,%7},{%8,%9},{%0,%1,%2,%3};"
        : "+f"(c[0]), "+f"(c[1]), "+f"(c[2]), "+f"(c[3])
        : "r"(a[0]), "r"(a[1]), "r"(a[2]), "r"(a[3]), "r"(b0), "r"(b1));
}
__device__ __forceinline__ void cp_async16(uint32_t saddr, const void* g) {
    asm volatile("cp.async.ca.shared.global [%0], [%1], 16;" :: "r"(saddr), "l"(g));
}
__device__ __forceinline__ void cp_async8(uint32_t saddr, const void* g) {
    asm volatile("cp.async.ca.shared.global [%0], [%1], 8;" :: "r"(saddr), "l"(g));
}
__device__ __forceinline__ void cp_commit() { asm volatile("cp.async.commit_group;"); }
template<int N> __device__ __forceinline__ void cp_wait() {
    asm volatile("cp.async.wait_group %0;" :: "n"(N));
}

// ---------------- K0 ----------------
__global__ void k_init(const float* __restrict__ Wfe, const float* __restrict__ bfe,
                       const float* __restrict__ Win_f) {
    int tid = threadIdx.x;
    if (tid < E_) g_cnt[tid] = 0;
    if (tid == 255) { g_minenc = 0xFFFFFFFFu; g_maxenc = 0u; }
    if (tid < 128) {
        int g = tid >> 4, f = (tid >> 2) & 3, s = tid & 3;
        float acc = 0.f;
        #pragma unroll 4
        for (int e = 0; e < 64; e++)
            acc += Wfe[(g * 4 + f) * 64 + e] * Win_f[(g * 64 + e) * 4 + s];
        g_M[tid] = acc;
    } else if (tid < 160) {
        int j = tid - 128; int g = j >> 2, s = j & 3;
        float acc = 0.f;
        #pragma unroll 4
        for (int e = 0; e < 64; e++)
            acc += bfe[g * 64 + e] * Win_f[(g * 64 + e) * 4 + s];
        g_C[j] = acc;
    }
}

__global__ void k_minmax(const float* __restrict__ feat, int n) {
    unsigned lmin = 0xFFFFFFFFu, lmax = 0u;
    for (int i = blockIdx.x * blockDim.x + threadIdx.x; i < n; i += gridDim.x * blockDim.x) {
        unsigned e = encf(feat[i]);
        lmin = min(lmin, e); lmax = max(lmax, e);
    }
    #pragma unroll
    for (int o = 16; o; o >>= 1) {
        lmin = min(lmin, __shfl_down_sync(0xFFFFFFFFu, lmin, o));
        lmax = max(lmax, __shfl_down_sync(0xFFFFFFFFu, lmax, o));
    }
    if ((threadIdx.x & 31) == 0) { atomicMin(&g_minenc, lmin); atomicMax(&g_maxenc, lmax); }
}

__global__ __launch_bounds__(256) void k_cvt_r(const float* __restrict__ H,
                                               const float* __restrict__ Wr1,
                                               const float* __restrict__ Win_h) {
    int id = blockIdx.x * 256 + threadIdx.x;
    if (id < 262144) {
        int t = id >> 6, p = id & 63;
        const float4* src = (const float4*)&H[(size_t)t * 512 + p * 8];
        float4 a = src[0], c = src[1];
        uint4 oh, ol;
        split_h2(a.x, a.y, oh.x, ol.x); split_h2(a.z, a.w, oh.y, ol.y);
        split_h2(c.x, c.y, oh.z, ol.z); split_h2(c.z, c.w, oh.w, ol.w);
        ((uint4*)g_Hh)[(size_t)t * 64 + p]  = oh;
        ((uint4*)g_Hlo)[(size_t)t * 64 + p] = ol;
    } else if (id < 278528) {
        int v = id - 262144;
        int r = v >> 6, c4 = (v & 63) * 4;
        const float* b0 = Wr1 + (size_t)(2 * r) * 256 + c4;
        const float* b1 = Wr1 + (size_t)(2 * r + 1) * 256 + c4;
        float4 a = *(const float4*)b0;
        float4 c = *(const float4*)b1;
        uint32_t hi, lo;
        split_h2(a.x, c.x, hi, lo); g_Wexth[r * 288 + c4 + 0] = hi; g_Wextl[r * 288 + c4 + 0] = lo;
        split_h2(a.y, c.y, hi, lo); g_Wexth[r * 288 + c4 + 1] = hi; g_Wextl[r * 288 + c4 + 1] = lo;
        split_h2(a.z, c.z, hi, lo); g_Wexth[r * 288 + c4 + 2] = hi; g_Wextl[r * 288 + c4 + 2] = lo;
        split_h2(a.w, c.w, hi, lo); g_Wexth[r * 288 + c4 + 3] = hi; g_Wextl[r * 288 + c4 + 3] = lo;
    } else if (id < 286720) {
        int v = id - 278528;
        int r = v >> 5, j = v & 31;
        int g = j >> 2, s = j & 3;
        float v0 = Win_h[((size_t)g * 512 + 2 * r) * 4 + s];
        float v1 = Win_h[((size_t)g * 512 + 2 * r + 1) * 4 + s];
        uint32_t hi, lo;
        split_h2(v0, v1, hi, lo);
        g_Wexth[r * 288 + 256 + j] = hi;
        g_Wextl[r * 288 + 256 + j] = lo;
    }
}

__global__ __launch_bounds__(256) void k_cvt_w(const float* __restrict__ We1,
                                               const float* __restrict__ We2) {
    int id = blockIdx.x * 256 + threadIdx.x;
    {
        int e = id >> 14, rem = id & 16383;
        int kr = rem >> 6, n = (rem & 63) * 4;
        const float* base = We1 + ((size_t)e * 512 + 2 * kr) * 256 + n;
        float4 a = *(const float4*)base;
        float4 c = *(const float4*)(base + 256);
        uint4 o;
        o.x = pack_h2(a.x, c.x); o.y = pack_h2(a.y, c.y);
        o.z = pack_h2(a.z, c.z); o.w = pack_h2(a.w, c.w);
        ((uint4*)g_We1h)[((size_t)e * 65536 + kr * 256 + n) >> 2] = o;
    }
    {
        int e = id >> 14, rem = id & 16383;
        int kr = rem >> 7, n = (rem & 127) * 4;
        const float* base = We2 + ((size_t)e * 256 + 2 * kr) * 512 + n;
        float4 a = *(const float4*)base;
        float4 c = *(const float4*)(base + 512);
        uint4 o;
        o.x = pack_h2(a.x, c.x); o.y = pack_h2(a.y, c.y);
        o.z = pack_h2(a.z, c.z); o.w = pack_h2(a.w, c.w);
        ((uint4*)g_We2h)[((size_t)e * 65536 + kr * 512 + n) >> 2] = o;
    }
}

// ---------------- K1: router GEMM + fused glog projection ----------------
#define GXP 36
#define GWP 104
#define GXBUF (64 * GXP)
#define GWBUF (32 * GWP)
#define GH_SMEM_BYTES ((2 * GXBUF + 2 * GWBUF) * 4)

__global__ __launch_bounds__(256) void k_gh(const float* __restrict__ br1,
                                            const float* __restrict__ Wr2) {
    extern __shared__ uint32_t gsm[];
    uint32_t* Xs2 = gsm;
    uint32_t* Ws2 = gsm + 2 * GXBUF;
    const int cg = blockIdx.x, base = blockIdx.y * 64, tid = threadIdx.x;
    const int w = tid >> 5, lane = tid & 31, gid = lane >> 2, tig = lane & 3;
    const int mwarp = (w & 1) * 32, nwarp = (w >> 1) * 24;
    const uint32_t xs_sb = (uint32_t)__cvta_generic_to_shared(Xs2);
    const uint32_t ws_sb = (uint32_t)__cvta_generic_to_shared(Ws2);

    float acc[2][3][4];
    #pragma unroll
    for (int m8 = 0; m8 < 2; m8++)
        #pragma unroll
        for (int n8 = 0; n8 < 3; n8++)
            #pragma unroll
            for (int c = 0; c < 4; c++) acc[m8][n8][c] = 0.f;

    #pragma unroll
    for (int pc = 0; pc < 2; pc++) {
        #pragma unroll
        for (int j = 0; j < 2; j++) {
            int u = j * 256 + tid, row = u >> 3, xq = (u & 7) * 4;
            cp_async16(xs_sb + (pc * GXBUF + row * GXP + xq) * 4,
                       &g_Hh[(size_t)(base + row) * 256 + pc * 32 + xq]);
        }
        #pragma unroll
        for (int j = 0; j < 3; j++) {
            int u = j * 256 + tid, kr = u / 24, c4 = (u % 24) * 4;
            cp_async16(ws_sb + (pc * GWBUF + kr * GWP + c4) * 4,
                       &g_Wexth[(pc * 32 + kr) * 288 + cg * 96 + c4]);
        }
        cp_commit();
    }

    for (int i = 0; i < 24; i++) {
        if (i < 23) cp_wait<1>(); else cp_wait<0>();
        __syncthreads();
        const uint32_t* Xb = Xs2 + (i & 1) * GXBUF;
        const uint32_t* Wb = Ws2 + (i & 1) * GWBUF;
        #pragma unroll
        for (int ks = 0; ks < 4; ks++) {
            const int kh = ks * 8;
            uint32_t a[2][4];
            #pragma unroll
            for (int m8 = 0; m8 < 2; m8++) {
                int r0 = mwarp + m8 * 16 + gid;
                a[m8][0] = Xb[r0 * GXP + kh + tig];
                a[m8][1] = Xb[(r0 + 8) * GXP + kh + tig];
                a[m8][2] = Xb[r0 * GXP + kh + tig + 4];
                a[m8][3] = Xb[(r0 + 8) * GXP + kh + tig + 4];
            }
            #pragma unroll
            for (int n8 = 0; n8 < 3; n8++) {
                int ncol = nwarp + n8 * 8 + gid;
                uint32_t b0 = Wb[(kh + tig) * GWP + ncol];
                uint32_t b1 = Wb[(kh + tig + 4) * GWP + ncol];
                mma16(acc[0][n8], a[0], b0, b1);
                mma16(acc[1][n8], a[1], b0, b1);
            }
        }
        __syncthreads();
        if (i + 2 < 24) {
            int kci = i + 2, buf = i & 1, seg = kci >> 3, kloc = kci & 7;
            const uint32_t* Asrc = (seg < 2) ? g_Hh : g_Hlo;
            const uint32_t* Wsrc = (seg == 1) ? g_Wextl : g_Wexth;
            #pragma unroll
            for (int j = 0; j < 2; j++) {
                int u = j * 256 + tid, row = u >> 3, xq = (u & 7) * 4;
                cp_async16(xs_sb + (buf * GXBUF + row * GXP + xq) * 4,
                           &Asrc[(size_t)(base + row) * 256 + kloc * 32 + xq]);
            }
            #pragma unroll
            for (int j = 0; j < 3; j++) {
                int u = j * 256 + tid, kr = u / 24, c4 = (u % 24) * 4;
                cp_async16(ws_sb + (buf * GWBUF + kr * GWP + c4) * 4,
                           &Wsrc[(kloc * 32 + kr) * 288 + cg * 96 + c4]);
            }
            cp_commit();
        }
    }

    float part[4][8];
    #pragma unroll
    for (int r = 0; r < 4; r++)
        #pragma unroll
        for (int q = 0; q < 8; q++) part[r][q] = 0.f;

    #pragma unroll
    for (int m8 = 0; m8 < 2; m8++) {
        #pragma unroll
        for (int c2 = 0; c2 < 2; c2++) {
            const int r = m8 * 2 + c2;
            const int row = base + mwarp + m8 * 16 + gid + (c2 ? 8 : 0);
            #pragma unroll
            for (int n8 = 0; n8 < 3; n8++) {
                int col0 = cg * 96 + nwarp + n8 * 8 + 2 * tig;
                float a0 = acc[m8][n8][c2 * 2 + 0];
                float a1 = acc[m8][n8][c2 * 2 + 1];
                if (col0 < 256) {
                    float v0 = gelu_exact(a0 + br1[col0]);
                    float v1 = gelu_exact(a1 + br1[col0 + 1]);
                    float4 w0a = *(const float4*)&Wr2[col0 * 8];
                    float4 w0b = *(const float4*)&Wr2[col0 * 8 + 4];
                    float4 w1a = *(const float4*)&Wr2[col0 * 8 + 8];
                    float4 w1b = *(const float4*)&Wr2[col0 * 8 + 12];
                    part[r][0] += v0 * w0a.x + v1 * w1a.x;
                    part[r][1] += v0 * w0a.y + v1 * w1a.y;
                    part[r][2] += v0 * w0a.z + v1 * w1a.z;
                    part[r][3] += v0 * w0a.w + v1 * w1a.w;
                    part[r][4] += v0 * w0b.x + v1 * w1b.x;
                    part[r][5] += v0 * w0b.y + v1 * w1b.y;
                    part[r][6] += v0 * w0b.z + v1 * w1b.z;
                    part[r][7] += v0 * w0b.w + v1 * w1b.w;
                } else {
                    *(float2*)&g_IL[(size_t)row * 32 + (col0 - 256)] = make_float2(a0, a1);
                }
            }
        }
    }

    #pragma unroll
    for (int r = 0; r < 4; r++)
        #pragma unroll
        for (int q = 0; q < 8; q++) {
            float v = part[r][q];
            v += __shfl_xor_sync(0xFFFFFFFFu, v, 1);
            v += __shfl_xor_sync(0xFFFFFFFFu, v, 2);
            part[r][q] = v;
        }

    __syncthreads();
    float* parts = (float*)gsm;
    if (tig == 0) {
        int wn = w >> 1;
        #pragma unroll
        for (int r = 0; r < 4; r++) {
            int rl = mwarp + (r >> 1) * 16 + gid + ((r & 1) ? 8 : 0);
            #pragma unroll
            for (int q = 0; q < 8; q++)
                parts[(wn * 64 + rl) * 8 + q] = part[r][q];
        }
    }
    __syncthreads();
    #pragma unroll
    for (int j = 0; j < 2; j++) {
        int idx = tid * 2 + j, row = idx >> 3, q = idx & 7;
        float v = parts[(0 * 64 + row) * 8 + q] + parts[(1 * 64 + row) * 8 + q]
                + parts[(2 * 64 + row) * 8 + q] + parts[(3 * 64 + row) * 8 + q];
        g_glogp[((size_t)cg * NTOK + base + row) * 8 + q] = v;
    }
}

// ---------------- K2: warp-per-token routing (glog precomputed) ----------------
__global__ __launch_bounds__(256) void k_route(
    const float* __restrict__ feat, const float* __restrict__ br2,
    const float* __restrict__ bin_b)
{
    const unsigned FULL = 0xFFFFFFFFu;
    const int t    = blockIdx.x * 8 + (threadIdx.x >> 5);
    const int lane = threadIdx.x & 31;
    const int g    = lane >> 2, s = lane & 3;

    float featv = feat[(size_t)t * 32 + lane];
    float ilv   = g_IL[(size_t)t * 32 + lane];
    float glog  = 0.f;
    if (lane < 8)
        glog = g_glogp[((size_t)0 * NTOK + t) * 8 + lane]
             + g_glogp[((size_t)1 * NTOK + t) * 8 + lane]
             + g_glogp[((size_t)2 * NTOK + t) * 8 + lane] + br2[lane];

    // score[g]: 1 to_ratio per lane, quad reduce
    const bool in01 = (decf(g_minenc) >= -1e-6f) && (decf(g_maxenc) <= 1.0f + 1e-6f);
    float r = in01 ? fminf(fmaxf(featv, 0.f), 1.f)
                   : fminf(fmaxf(0.5f * (1.f + erff(featv * 0.70710678118654752f)), 0.f), 1.f);
    r += __shfl_xor_sync(FULL, r, 1);
    r += __shfl_xor_sync(FULL, r, 2);
    float score = r * 0.25f;

    // ilog for this lane's (g, s)
    int qb = lane & ~3;
    float f0 = __shfl_sync(FULL, featv, qb + 0);
    float f1 = __shfl_sync(FULL, featv, qb + 1);
    float f2 = __shfl_sync(FULL, featv, qb + 2);
    float f3 = __shfl_sync(FULL, featv, qb + 3);
    float q0 = g_C[lane]
             + f0 * g_M[g * 16 + 0 * 4 + s] + f1 * g_M[g * 16 + 1 * 4 + s]
             + f2 * g_M[g * 16 + 2 * 4 + s] + f3 * g_M[g * 16 + 3 * 4 + s];
    float cc = (float)s * (1.0f / 3.0f);
    float dd = score - cc;
    float ilog = q0 + ilv + bin_b[lane] - SHARP_ * dd * dd;

    // gw: top-2 softmax over 8 group logits (thresholds via shfl, 8 exps total)
    float m1 = -FLT_MAX, m2 = -FLT_MAX;
    #pragma unroll
    for (int q = 0; q < 8; q++) {
        float v = __shfl_sync(FULL, glog, q);
        if (v > m1) { m2 = m1; m1 = v; } else if (v > m2) m2 = v;
    }
    float gex = (lane < 8 && glog >= m2) ? expf(glog - m1) : 0.f;
    float gsum = gex;
    gsum += __shfl_xor_sync(FULL, gsum, 1);
    gsum += __shfl_xor_sync(FULL, gsum, 2);
    gsum += __shfl_xor_sync(FULL, gsum, 4);
    float gwv = __shfl_sync(FULL, gex, g) / __shfl_sync(FULL, gsum, 0);

    // cw: top-2 softmax within quad (1 exp per lane)
    float n1 = -FLT_MAX, n2 = -FLT_MAX;
    #pragma unroll
    for (int i = 0; i < 4; i++) {
        float v = __shfl_sync(FULL, ilog, qb + i);
        if (v > n1) { n2 = n1; n1 = v; } else if (v > n2) n2 = v;
    }
    float ex = (ilog >= n2) ? expf(ilog - n1) : 0.f;
    float esum = ex;
    esum += __shfl_xor_sync(FULL, esum, 1);
    esum += __shfl_xor_sync(FULL, esum, 2);
    float cwv = ex / esum;

    float wv = gwv * cwv;

    unsigned act = __ballot_sync(FULL, wv > 0.f);
    if (lane == 0) g_scnt[t] = min(__popc(act), SLOTS);
    if (wv > 0.f) {
        int j = __popc(act & ((1u << lane) - 1u));
        if (j < SLOTS) {
            g_w4[t * SLOTS + j] = wv;
            g_e4[t * SLOTS + j] = lane;
            int pos = atomicAdd(&g_cnt[lane], 1);
            g_tokid[lane * NTOK + pos] = t;
            g_slot [lane * NTOK + pos] = t * SLOTS + j;
        }
    }
}

// ---------------- K3: expert FFN, fp16 mma + cp.async double-buffer (round-13 best) ----------------
#define XP2 20
#define WP2 264
#define HP2 132
#define XBUF (64 * XP2)
#define WBUF (16 * WP2)
#define OFF_TOK   0
#define OFF_SLOT  64
#define OFF_B1    128
#define OFF_XS    384
#define OFF_WS    (OFF_XS + 2 * XBUF)
#define OFF_H1    (OFF_WS + 2 * WBUF)
#define SMEM_WORDS (OFF_H1 + 64 * HP2)
#define SMEM_BYTES (SMEM_WORDS * 4)

__global__ __launch_bounds__(256, 2) void k_expert_mma(const float* __restrict__ be1)
{
    extern __shared__ uint32_t smu[];
    int*      tok_s  = (int*)smu;
    int*      slot_s = (int*)(smu + OFF_SLOT);
    float*    bias_s = (float*)(smu + OFF_B1);
    uint32_t* Xs2    = smu + OFF_XS;
    uint32_t* Ws2    = smu + OFF_WS;
    uint32_t* H1s2   = smu + OFF_H1;

    const int e = blockIdx.x;
    const int n = g_cnt[e];
    const int base = blockIdx.y * 64;
    if (base >= n) return;

    const int tid  = threadIdx.x;
    const int w    = tid >> 5;
    const int lane = tid & 31;
    const int gid  = lane >> 2;
    const int tig  = lane & 3;
    const int mwarp = (w & 1) * 32;
    const int nwarp = (w >> 1) * 64;

    if (tid < 64) {
        int idx = base + tid;
        if (idx < n) { tok_s[tid] = g_tokid[e * NTOK + idx]; slot_s[tid] = g_slot[e * NTOK + idx]; }
        else         { tok_s[tid] = g_tokid[e * NTOK + base]; slot_s[tid] = DUMP_SLOT; }
    }
    bias_s[tid] = be1[e * 256 + tid];
    __syncthreads();

    const uint32_t xs_sb = (uint32_t)__cvta_generic_to_shared(Xs2);
    const uint32_t ws_sb = (uint32_t)__cvta_generic_to_shared(Ws2);
    const uint32_t* W1h = g_We1h + (size_t)e * 65536;
    const uint32_t* W2h = g_We2h + (size_t)e * 65536;

    float acc[2][8][4];

    #pragma unroll
    for (int m8 = 0; m8 < 2; m8++)
        #pragma unroll
        for (int n8 = 0; n8 < 8; n8++)
            #pragma unroll
            for (int c = 0; c < 4; c++) acc[m8][n8][c] = 0.f;

    #pragma unroll
    for (int pc = 0; pc < 2; pc++) {
        #pragma unroll
        for (int j = 0; j < 2; j++) {
            int u = tid * 2 + j;
            int t = u >> 3, p = u & 7;
            cp_async8(xs_sb + (pc * XBUF + t * XP2 + p * 2) * 4,
                      &g_Hh[(size_t)tok_s[t] * 256 + pc * 16 + p * 2]);
        }
        #pragma unroll
        for (int j = 0; j < 4; j++) {
            int u = j * 256 + tid;
            int kr = u >> 6, c = (u & 63) * 4;
            cp_async16(ws_sb + (pc * WBUF + kr * WP2 + c) * 4,
                       &W1h[(pc * 16 + kr) * 256 + c]);
        }
        cp_commit();
    }

    for (int i = 0; i < 16; i++) {
        if (i < 15) cp_wait<1>(); else cp_wait<0>();
        __syncthreads();
        const uint32_t* Xb = Xs2 + (i & 1) * XBUF;
        const uint32_t* Wb = Ws2 + (i & 1) * WBUF;

        #pragma unroll
        for (int ks = 0; ks < 2; ks++) {
            const int kh = ks * 8;
            uint32_t a[2][4];
            #pragma unroll
            for (int m8 = 0; m8 < 2; m8++) {
                int r0 = mwarp + m8 * 16 + gid;
                a[m8][0] = Xb[r0 * XP2 + kh + tig];
                a[m8][1] = Xb[(r0 + 8) * XP2 + kh + tig];
                a[m8][2] = Xb[r0 * XP2 + kh + tig + 4];
                a[m8][3] = Xb[(r0 + 8) * XP2 + kh + tig + 4];
            }
            #pragma unroll
            for (int n8 = 0; n8 < 8; n8++) {
                int ncol = nwarp + n8 * 8 + gid;
                uint32_t b0 = Wb[(kh + tig) * WP2 + ncol];
                uint32_t b1 = Wb[(kh + tig + 4) * WP2 + ncol];
                mma16(acc[0][n8], a[0], b0, b1);
                mma16(acc[1][n8], a[1], b0, b1);
            }
        }
        __syncthreads();

        if (i + 2 < 16) {
            int kci = i + 2, buf = i & 1;
            #pragma unroll
            for (int j = 0; j < 2; j++) {
                int u = tid * 2 + j;
                int t = u >> 3, p = u & 7;
                cp_async8(xs_sb + (buf * XBUF + t * XP2 + p * 2) * 4,
                          &g_Hh[(size_t)tok_s[t] * 256 + kci * 16 + p * 2]);
            }
            #pragma unroll
            for (int j = 0; j < 4; j++) {
                int u = j * 256 + tid;
                int kr = u >> 6, c = (u & 63) * 4;
                cp_async16(ws_sb + (buf * WBUF + kr * WP2 + c) * 4,
                           &W1h[(kci * 16 + kr) * 256 + c]);
            }
            cp_commit();
        }
    }

    #pragma unroll
    for (int m8 = 0; m8 < 2; m8++) {
        #pragma unroll
        for (int c2 = 0; c2 < 2; c2++) {
            int row = mwarp + m8 * 16 + gid + (c2 ? 8 : 0);
            #pragma unroll
            for (int n8 = 0; n8 < 8; n8++) {
                int col0 = nwarp + n8 * 8 + 2 * tig;
                float v0 = gelu_exact(acc[m8][n8][c2 * 2 + 0] + bias_s[col0]);
                float v1 = gelu_exact(acc[m8][n8][c2 * 2 + 1] + bias_s[col0 + 1]);
                H1s2[row * HP2 + (col0 >> 1)] = pack_h2(v0, v1);
            }
        }
    }
    __syncthreads();

    #pragma unroll
    for (int half = 0; half < 2; half++) {
        #pragma unroll
        for (int m8 = 0; m8 < 2; m8++)
            #pragma unroll
            for (int n8 = 0; n8 < 8; n8++)
                #pragma unroll
                for (int c = 0; c < 4; c++) acc[m8][n8][c] = 0.f;

        #pragma unroll
        for (int pc = 0; pc < 2; pc++) {
            #pragma unroll
            for (int j = 0; j < 4; j++) {
                int u = j * 256 + tid;
                int kr = u >> 6, c = (u & 63) * 4;
                cp_async16(ws_sb + (pc * WBUF + kr * WP2 + c) * 4,
                           &W2h[(size_t)(pc * 16 + kr) * 512 + half * 256 + c]);
            }
            cp_commit();
        }

        for (int i = 0; i < 8; i++) {
            if (i < 7) cp_wait<1>(); else cp_wait<0>();
            __syncthreads();
            const uint32_t* Wb = Ws2 + (i & 1) * WBUF;
            const int kc = i * 32;

            #pragma unroll
            for (int ks = 0; ks < 2; ks++) {
                const int kh = ks * 8;
                const int ah = (kc >> 1) + kh;
                uint32_t a[2][4];
                #pragma unroll
                for (int m8 = 0; m8 < 2; m8++) {
                    int r0 = mwarp + m8 * 16 + gid;
                    a[m8][0] = H1s2[r0 * HP2 + ah + tig];
                    a[m8][1] = H1s2[(r0 + 8) * HP2 + ah + tig];
                    a[m8][2] = H1s2[r0 * HP2 + ah + tig + 4];
                    a[m8][3] = H1s2[(r0 + 8) * HP2 + ah + tig + 4];
                }
                #pragma unroll
                for (int n8 = 0; n8 < 8; n8++) {
                    int ncol = nwarp + n8 * 8 + gid;
                    uint32_t b0 = Wb[(kh + tig) * WP2 + ncol];
                    uint32_t b1 = Wb[(kh + tig + 4) * WP2 + ncol];
                    mma16(acc[0][n8], a[0], b0, b1);
                    mma16(acc[1][n8], a[1], b0, b1);
                }
            }
            __syncthreads();

            if (i + 2 < 8) {
                int kci = i + 2, buf = i & 1;
                #pragma unroll
                for (int j = 0; j < 4; j++) {
                    int u = j * 256 + tid;
                    int kr = u >> 6, c = (u & 63) * 4;
                    cp_async16(ws_sb + (buf * WBUF + kr * WP2 + c) * 4,
                               &W2h[(size_t)(kci * 16 + kr) * 512 + half * 256 + c]);
                }
                cp_commit();
            }
        }

        #pragma unroll
        for (int m8 = 0; m8 < 2; m8++) {
            #pragma unroll
            for (int c2 = 0; c2 < 2; c2++) {
                int row = mwarp + m8 * 16 + gid + (c2 ? 8 : 0);
                int sl = slot_s[row];
                float* dst = &g_part[(size_t)sl * 512 + half * 256 + nwarp + 2 * tig];
                #pragma unroll
                for (int n8 = 0; n8 < 8; n8++) {
                    float2 v = make_float2(acc[m8][n8][c2 * 2 + 0], acc[m8][n8][c2 * 2 + 1]);
                    *(float2*)(dst + n8 * 8) = v;
                }
            }
        }
    }
}

// ---------------- K4: gather ----------------
__global__ __launch_bounds__(128) void k_gather(const float* __restrict__ be2,
                                                float* __restrict__ y) {
    const int t = blockIdx.x, tid = threadIdx.x;
    const int d = tid * 4;
    const int cnt = g_scnt[t];
    float4 acc = make_float4(0.f, 0.f, 0.f, 0.f);
    for (int j = 0; j < cnt; j++) {
        float wv = g_w4[t * SLOTS + j];
        int   ev = g_e4[t * SLOTS + j];
        float4 p = *(const float4*)&g_part[(size_t)(t * SLOTS + j) * 512 + d];
        float4 b = *(const float4*)&be2[ev * 512 + d];
        acc.x += wv * (p.x + b.x); acc.y += wv * (p.y + b.y);
        acc.z += wv * (p.z + b.z); acc.w += wv * (p.w + b.w);
    }
    *(float4*)&y[(size_t)t * 512 + d] = acc;
}

// ---------------- launch ----------------
extern "C" void kernel_launch(void* const* d_in, const int* in_sizes, int n_in,
                              void* d_out, int out_size) {
    (void)in_sizes; (void)n_in; (void)out_size;
    const float* hidden = (const float*)d_in[0];
    const float* feat   = (const float*)d_in[1];
    const float* Wr1    = (const float*)d_in[3];
    const float* br1    = (const float*)d_in[4];
    const float* Wr2    = (const float*)d_in[5];
    const float* br2    = (const float*)d_in[6];
    const float* Wfe    = (const float*)d_in[7];
    const float* bfe    = (const float*)d_in[8];
    const float* Win_h  = (const float*)d_in[9];
    const float* Win_f  = (const float*)d_in[10];
    const float* bin_b  = (const float*)d_in[11];
    const float* We1    = (const float*)d_in[12];
    const float* be1    = (const float*)d_in[13];
    const float* We2    = (const float*)d_in[14];
    const float* be2    = (const float*)d_in[15];
    float* y = (float*)d_out;

    static bool inited = false;
    static cudaStream_t s2;
    static cudaEvent_t evFork, evJoin;
    if (!inited) {
        cudaFuncSetAttribute(k_expert_mma, cudaFuncAttributeMaxDynamicSharedMemorySize, SMEM_BYTES);
        cudaFuncSetAttribute(k_gh, cudaFuncAttributeMaxDynamicSharedMemorySize, GH_SMEM_BYTES);
        cudaStreamCreateWithFlags(&s2, cudaStreamNonBlocking);
        cudaEventCreateWithFlags(&evFork, cudaEventDisableTiming);
        cudaEventCreateWithFlags(&evJoin, cudaEventDisableTiming);
        inited = true;
    }

    cudaEventRecord(evFork, 0);
    cudaStreamWaitEvent(s2, evFork, 0);
    k_init<<<1, 256, 0, s2>>>(Wfe, bfe, Win_f);
    k_minmax<<<64, 256, 0, s2>>>(feat, NTOK * 32);
    k_cvt_w<<<2048, 256, 0, s2>>>(We1, We2);
    cudaEventRecord(evJoin, s2);

    k_cvt_r<<<1120, 256>>>(hidden, Wr1, Win_h);
    k_gh<<<dim3(3, NTOK / 64), 256, GH_SMEM_BYTES>>>(br1, Wr2);

    cudaStreamWaitEvent(0, evJoin, 0);
    k_route<<<NTOK / 8, 256>>>(feat, br2, bin_b);
    k_expert_mma<<<dim3(E_, NTOK / 64), 256, SMEM_BYTES>>>(be1);
    k_gather<<<NTOK, 128>>>(be2, y);
}